// round 1
// baseline (speedup 1.0000x reference)
#include <cuda_runtime.h>
#include <math.h>
#include <stdint.h>

#define B_   8
#define LQ_  512
#define LK_  2048
#define E_   512
#define H_   8
#define HD_  64
#define TOPK_ 20

// ---------------- scratch (static device globals; no allocs) ----------------
__device__ float g_Qh[(size_t)B_ * H_ * LQ_ * HD_];   //  8 MB  [b,h,lq,hd]
__device__ float g_Kh[(size_t)B_ * H_ * LK_ * HD_];   // 32 MB  [b,h,lk,hd]
__device__ float g_Vh[(size_t)B_ * H_ * LK_ * HD_];   // 32 MB  [b,h,lk,hd]
__device__ float g_AO[(size_t)B_ * LQ_ * E_];         //  8 MB  [b,lq,e]

// ---------------------------------------------------------------------------
// GEMM  Y = X @ W^T   (X: [M, 512], W: [512, 512] row-major; "NT" layout:
// both operands K-contiguous).  BM=128, BN=64, BK=16, 256 threads, 8x4 micro.
// MODE 0: scatter into head layout [b,h,l,hd]   (L = rows per batch)
// MODE 1: plain row-major + bias[n] + resid[m,n]
// ---------------------------------------------------------------------------
template <int MODE>
__global__ void __launch_bounds__(256)
gemm_nt(const float* __restrict__ X, const float* __restrict__ W,
        float* __restrict__ Y, int L,
        const float* __restrict__ bias, const float* __restrict__ resid)
{
    __shared__ __align__(16) float As[16][132];  // transposed: As[k][m]
    __shared__ __align__(16) float Bs[16][68];   // transposed: Bs[k][n]

    const int tid = threadIdx.x;
    const int m0  = blockIdx.x * 128;
    const int n0  = blockIdx.y * 64;
    const int ty  = tid >> 4;   // 0..15 -> 8 rows each
    const int tx  = tid & 15;   // 0..15 -> 4 cols each

    float acc[8][4];
#pragma unroll
    for (int i = 0; i < 8; i++)
#pragma unroll
        for (int j = 0; j < 4; j++) acc[i][j] = 0.f;

    for (int kt = 0; kt < E_; kt += 16) {
        // load A tile: 128x16 floats = 512 float4, 2 per thread
#pragma unroll
        for (int i = 0; i < 2; i++) {
            int f   = tid + i * 256;
            int row = f >> 2;
            int c4  = (f & 3) * 4;
            float4 v = *(const float4*)(X + (size_t)(m0 + row) * E_ + kt + c4);
            As[c4 + 0][row] = v.x;
            As[c4 + 1][row] = v.y;
            As[c4 + 2][row] = v.z;
            As[c4 + 3][row] = v.w;
        }
        // load B tile: 64x16 floats = 256 float4, 1 per thread
        {
            int row = tid >> 2;
            int c4  = (tid & 3) * 4;
            float4 v = *(const float4*)(W + (size_t)(n0 + row) * E_ + kt + c4);
            Bs[c4 + 0][row] = v.x;
            Bs[c4 + 1][row] = v.y;
            Bs[c4 + 2][row] = v.z;
            Bs[c4 + 3][row] = v.w;
        }
        __syncthreads();

#pragma unroll
        for (int kk = 0; kk < 16; kk++) {
            float4 a0 = *(const float4*)&As[kk][ty * 8];
            float4 a1 = *(const float4*)&As[kk][ty * 8 + 4];
            float4 bv = *(const float4*)&Bs[kk][tx * 4];
            float a[8] = {a0.x, a0.y, a0.z, a0.w, a1.x, a1.y, a1.z, a1.w};
            float b[4] = {bv.x, bv.y, bv.z, bv.w};
#pragma unroll
            for (int i = 0; i < 8; i++)
#pragma unroll
                for (int j = 0; j < 4; j++) acc[i][j] += a[i] * b[j];
        }
        __syncthreads();
    }

#pragma unroll
    for (int i = 0; i < 8; i++) {
        int m = m0 + ty * 8 + i;
#pragma unroll
        for (int j = 0; j < 4; j++) {
            int   n = n0 + tx * 4 + j;
            float v = acc[i][j];
            if (MODE == 0) {
                int bb = m / L, l = m % L;
                int h  = n >> 6, hd = n & 63;
                Y[(((size_t)(bb * H_ + h) * L + l) << 6) + hd] = v;
            } else {
                v += bias[n] + resid[(size_t)m * E_ + n];
                Y[(size_t)m * E_ + n] = v;
            }
        }
    }
}

// ---------------------------------------------------------------------------
// Fused attention: per (b,h,q) row — scores (2048 logits in regs), softmax
// stats, top-20 selection (20x block argmax), sparse AV gather.
// grid (LQ, H, B), 256 threads. Each thread owns 8 consecutive keys.
// ---------------------------------------------------------------------------
__global__ void __launch_bounds__(256) attn_topk_kernel()
{
    const int tid = threadIdx.x;
    const int qi  = blockIdx.x;
    const int h   = blockIdx.y;
    const int b   = blockIdx.z;
    const int bh  = b * H_ + h;

    __shared__ __align__(16) float qv[64];
    __shared__ float s_red[8];
    __shared__ int   s_redi[8];
    __shared__ int   s_bi;
    __shared__ float top_w[TOPK_];
    __shared__ int   top_i[TOPK_];

    if (tid < 64)
        qv[tid] = g_Qh[((size_t)bh * LQ_ + qi) * 64 + tid] * 0.125f;  // 1/sqrt(64)
    __syncthreads();

    const float4* q4 = (const float4*)qv;
    const int base = tid * 8;

    float ls[8];
    float lmax = -INFINITY;
#pragma unroll
    for (int jj = 0; jj < 8; jj++) {
        const float4* kp = (const float4*)(g_Kh + ((size_t)bh * LK_ + base + jj) * 64);
        float s0 = 0.f, s1 = 0.f, s2 = 0.f, s3 = 0.f;
#pragma unroll
        for (int c = 0; c < 16; c += 4) {
            float4 k0 = kp[c + 0], k1 = kp[c + 1], k2 = kp[c + 2], k3 = kp[c + 3];
            float4 p0 = q4[c + 0], p1 = q4[c + 1], p2 = q4[c + 2], p3 = q4[c + 3];
            s0 += k0.x * p0.x + k0.y * p0.y + k0.z * p0.z + k0.w * p0.w;
            s1 += k1.x * p1.x + k1.y * p1.y + k1.z * p1.z + k1.w * p1.w;
            s2 += k2.x * p2.x + k2.y * p2.y + k2.z * p2.z + k2.w * p2.w;
            s3 += k3.x * p3.x + k3.y * p3.y + k3.z * p3.z + k3.w * p3.w;
        }
        float s = (s0 + s1) + (s2 + s3);
        ls[jj] = s;
        lmax = fmaxf(lmax, s);
    }

    const int lane = tid & 31, wid = tid >> 5;

    // block max
#pragma unroll
    for (int o = 16; o; o >>= 1) lmax = fmaxf(lmax, __shfl_xor_sync(0xffffffffu, lmax, o));
    if (lane == 0) s_red[wid] = lmax;
    __syncthreads();
    float m = s_red[0];
#pragma unroll
    for (int w = 1; w < 8; w++) m = fmaxf(m, s_red[w]);
    __syncthreads();

    // block sum of exp
    float lsum = 0.f;
#pragma unroll
    for (int jj = 0; jj < 8; jj++) lsum += __expf(ls[jj] - m);
#pragma unroll
    for (int o = 16; o; o >>= 1) lsum += __shfl_xor_sync(0xffffffffu, lsum, o);
    if (lane == 0) s_red[wid] = lsum;
    __syncthreads();
    float denom = 0.f;
#pragma unroll
    for (int w = 0; w < 8; w++) denom += s_red[w];
    const float inv_denom = 1.f / denom;
    __syncthreads();

    // top-20 by iterative block argmax (monotone: top-k of logits == of probs)
    for (int t = 0; t < TOPK_; t++) {
        float bv = -INFINITY;
        int   bi = 0;
#pragma unroll
        for (int jj = 0; jj < 8; jj++) {
            if (ls[jj] > bv) { bv = ls[jj]; bi = base + jj; }
        }
#pragma unroll
        for (int o = 16; o; o >>= 1) {
            float ov = __shfl_xor_sync(0xffffffffu, bv, o);
            int   oi = __shfl_xor_sync(0xffffffffu, bi, o);
            if (ov > bv || (ov == bv && oi < bi)) { bv = ov; bi = oi; }
        }
        if (lane == 0) { s_red[wid] = bv; s_redi[wid] = bi; }
        __syncthreads();
        if (tid == 0) {
            float bbv = s_red[0];
            int   bbi = s_redi[0];
#pragma unroll
            for (int w = 1; w < 8; w++) {
                if (s_red[w] > bbv || (s_red[w] == bbv && s_redi[w] < bbi)) {
                    bbv = s_red[w]; bbi = s_redi[w];
                }
            }
            top_i[t] = bbi;
            top_w[t] = __expf(bbv - m) * inv_denom;
            s_bi = bbi;
        }
        __syncthreads();
        const int wi = s_bi;
#pragma unroll
        for (int jj = 0; jj < 8; jj++)
            if (base + jj == wi) ls[jj] = -INFINITY;
        // next write of s_red is gated by the tid==0 read->sync above; safe
    }

    // sparse AV: out[hd] = sum_t w_t * V[bh, idx_t, hd]
    if (tid < 64) {
        float acc = 0.f;
#pragma unroll
        for (int t = 0; t < TOPK_; t++)
            acc += top_w[t] * g_Vh[((size_t)bh * LK_ + top_i[t]) * 64 + tid];
        g_AO[((size_t)b * LQ_ + qi) * E_ + h * 64 + tid] = acc;
    }
}

// ---------------------------------------------------------------------------
extern "C" void kernel_launch(void* const* d_in, const int* in_sizes, int n_in,
                              void* d_out, int out_size)
{
    const float* q  = (const float*)d_in[0];
    const float* k  = (const float*)d_in[1];
    const float* v  = (const float*)d_in[2];
    const float* Wq = (const float*)d_in[3];
    const float* Wk = (const float*)d_in[4];
    const float* Wv = (const float*)d_in[5];
    const float* Wo = (const float*)d_in[6];
    const float* bo = (const float*)d_in[7];
    float* out = (float*)d_out;

    float *pQh, *pKh, *pVh, *pAO;
    cudaGetSymbolAddress((void**)&pQh, g_Qh);
    cudaGetSymbolAddress((void**)&pKh, g_Kh);
    cudaGetSymbolAddress((void**)&pVh, g_Vh);
    cudaGetSymbolAddress((void**)&pAO, g_AO);

    // projections into head layout
    gemm_nt<0><<<dim3((B_ * LQ_) / 128, E_ / 64), 256>>>(q, Wq, pQh, LQ_, nullptr, nullptr);
    gemm_nt<0><<<dim3((B_ * LK_) / 128, E_ / 64), 256>>>(k, Wk, pKh, LK_, nullptr, nullptr);
    gemm_nt<0><<<dim3((B_ * LK_) / 128, E_ / 64), 256>>>(v, Wv, pVh, LK_, nullptr, nullptr);

    // fused scores + softmax stats + top-20 + sparse AV
    attn_topk_kernel<<<dim3(LQ_, H_, B_), 256>>>();

    // output projection + bias + residual(q)
    gemm_nt<1><<<dim3((B_ * LQ_) / 128, E_ / 64), 256>>>(pAO, Wo, out, LQ_, bo, q);
}

// round 6
// speedup vs baseline: 3.5195x; 3.5195x over previous
#include <cuda_runtime.h>
#include <math.h>
#include <stdint.h>

#define B_    8
#define LQ_   512
#define LK_   2048
#define E_    512
#define H_    8
#define HD_   64
#define TOPK_ 20

// ---------------- scratch (static device globals; no allocs) ----------------
__device__ __align__(128) float g_Qh[(size_t)B_ * H_ * LQ_ * HD_];   //  8 MB  [b,h,lq,hd]
__device__ __align__(128) float g_Kh[(size_t)B_ * H_ * LK_ * HD_];   // 32 MB  [b,h,lk,hd]
__device__ __align__(128) float g_Vh[(size_t)B_ * H_ * LK_ * HD_];   // 32 MB  [b,h,lk,hd]
__device__ __align__(128) float g_AO[(size_t)B_ * LQ_ * E_];         //  8 MB  [b,lq,e]

// ---------------------------------------------------------------------------
// GEMM  Y = X @ W^T  (X: [M,512], W: [512,512], both row-major K-contiguous)
// BM=128, BN=128, BK=16, 256 threads, 8x8 micro-tile, 2 CTAs/SM.
// MODE 0: scatter into head layout [b,h,l,hd]   (L = rows per batch)
// MODE 1: row-major + bias[n] + resid[m,n]
// ---------------------------------------------------------------------------
template <int MODE>
__global__ void __launch_bounds__(256, 2)
gemm_nt(const float* __restrict__ X, const float* __restrict__ W,
        float* __restrict__ Y, int L,
        const float* __restrict__ bias, const float* __restrict__ resid)
{
    __shared__ __align__(16) float As[16][132];  // transposed: As[k][m]
    __shared__ __align__(16) float Bs[16][132];  // transposed: Bs[k][n]

    const int tid = threadIdx.x;
    const int m0  = blockIdx.x * 128;
    const int n0  = blockIdx.y * 128;
    const int ty  = tid >> 4;   // 0..15
    const int tx  = tid & 15;   // 0..15

    float acc[8][8];
#pragma unroll
    for (int i = 0; i < 8; i++)
#pragma unroll
        for (int j = 0; j < 8; j++) acc[i][j] = 0.f;

    for (int kt = 0; kt < E_; kt += 16) {
        // A tile: 128x16 = 512 float4, 2 per thread
#pragma unroll
        for (int i = 0; i < 2; i++) {
            int f   = tid + i * 256;
            int row = f >> 2;
            int c4  = (f & 3) * 4;
            float4 v = *(const float4*)(X + (size_t)(m0 + row) * E_ + kt + c4);
            As[c4 + 0][row] = v.x;
            As[c4 + 1][row] = v.y;
            As[c4 + 2][row] = v.z;
            As[c4 + 3][row] = v.w;
        }
        // B tile: 128x16 = 512 float4, 2 per thread
#pragma unroll
        for (int i = 0; i < 2; i++) {
            int f   = tid + i * 256;
            int row = f >> 2;
            int c4  = (f & 3) * 4;
            float4 v = *(const float4*)(W + (size_t)(n0 + row) * E_ + kt + c4);
            Bs[c4 + 0][row] = v.x;
            Bs[c4 + 1][row] = v.y;
            Bs[c4 + 2][row] = v.z;
            Bs[c4 + 3][row] = v.w;
        }
        __syncthreads();

#pragma unroll
        for (int kk = 0; kk < 16; kk++) {
            float a[8], b[8];
            *(float4*)(a)     = *(const float4*)&As[kk][ty * 8];
            *(float4*)(a + 4) = *(const float4*)&As[kk][ty * 8 + 4];
            *(float4*)(b)     = *(const float4*)&Bs[kk][tx * 8];
            *(float4*)(b + 4) = *(const float4*)&Bs[kk][tx * 8 + 4];
#pragma unroll
            for (int i = 0; i < 8; i++)
#pragma unroll
                for (int j = 0; j < 8; j++) acc[i][j] = fmaf(a[i], b[j], acc[i][j]);
        }
        __syncthreads();
    }

#pragma unroll
    for (int i = 0; i < 8; i++) {
        int m = m0 + ty * 8 + i;
#pragma unroll
        for (int j0 = 0; j0 < 8; j0 += 4) {
            int n = n0 + tx * 8 + j0;
            float4 v = make_float4(acc[i][j0], acc[i][j0 + 1], acc[i][j0 + 2], acc[i][j0 + 3]);
            if (MODE == 0) {
                int bb = m / L, l = m - bb * L;
                int h  = n >> 6, hd = n & 63;
                *(float4*)&Y[(((size_t)(bb * H_ + h) * L + l) << 6) + hd] = v;
            } else {
                float4 bi4 = *(const float4*)&bias[n];
                float4 r4  = *(const float4*)&resid[(size_t)m * E_ + n];
                v.x += bi4.x + r4.x;
                v.y += bi4.y + r4.y;
                v.z += bi4.z + r4.z;
                v.w += bi4.w + r4.w;
                *(float4*)&Y[(size_t)m * E_ + n] = v;
            }
        }
    }
}

// ---------------------------------------------------------------------------
// Attention v2: block = (b, h, 16 queries), 512 threads.
// Phase 1: QK scores (each thread: 16q x 4k in regs) -> smem [16][2048]
// Phase 2: warp-per-query softmax stats + top-20 (chunked lane maxima)
// Phase 3: sparse AV gather (16q x 64d, float4 per thread)
// ---------------------------------------------------------------------------
__global__ void __launch_bounds__(512, 1) attn_topk2()
{
    extern __shared__ float sm[];
    float* scores = sm;                    // 16*2048 floats
    float* Qs     = sm + 16 * 2048;        // 1024 floats [q][d]
    float* swl    = Qs + 1024;             // 16*20 weights
    int*   sil    = (int*)(swl + 320);     // 16*20 indices

    const int tid  = threadIdx.x;
    const int lane = tid & 31;
    const int wid  = tid >> 5;             // 0..15
    const int q0   = blockIdx.x * 16;
    const int h    = blockIdx.y;
    const int b    = blockIdx.z;
    const int bh   = b * H_ + h;

    // ---- load Q tile (scaled) ----
    {
        const float* qsrc = g_Qh + ((size_t)bh * LQ_ + q0) * 64;
        for (int i = tid; i < 1024; i += 512) Qs[i] = qsrc[i] * 0.125f;  // 1/sqrt(64)
    }
    __syncthreads();

    // ---- Phase 1: scores. thread owns key (kq*512 + tid) for kq=0..3 ----
    float acc[16][4];
#pragma unroll
    for (int q = 0; q < 16; q++)
#pragma unroll
        for (int kq = 0; kq < 4; kq++) acc[q][kq] = 0.f;

#pragma unroll
    for (int kq = 0; kq < 4; kq++) {
        const float* kp = g_Kh + ((size_t)bh * LK_ + kq * 512 + tid) * 64;
#pragma unroll 1
        for (int dc = 0; dc < 16; dc++) {
            float4 kv = *(const float4*)(kp + dc * 4);
#pragma unroll
            for (int q = 0; q < 16; q++) {
                float4 qv = *(const float4*)&Qs[q * 64 + dc * 4];
                float t = acc[q][kq];
                t = fmaf(qv.x, kv.x, t);
                t = fmaf(qv.y, kv.y, t);
                t = fmaf(qv.z, kv.z, t);
                t = fmaf(qv.w, kv.w, t);
                acc[q][kq] = t;
            }
        }
    }
#pragma unroll
    for (int kq = 0; kq < 4; kq++)
#pragma unroll
        for (int q = 0; q < 16; q++)
            scores[q * 2048 + kq * 512 + tid] = acc[q][kq];
    __syncthreads();

    // ---- Phase 2: per-warp softmax stats + top-20 for query q = wid ----
    {
        float* row = scores + wid * 2048;   // lane owns k = lane + 32*i, i<64

        float cm[4]; int ci[4];             // chunk maxima (chunks of 16 strided elems)
        float m = -INFINITY;
#pragma unroll
        for (int c = 0; c < 4; c++) {
            float bv = -INFINITY; int bi = 0;
            for (int i = 0; i < 16; i++) {
                int k = lane + 32 * (c * 16 + i);
                float v = row[k];
                if (v > bv) { bv = v; bi = k; }
            }
            cm[c] = bv; ci[c] = bi;
            m = fmaxf(m, bv);
        }
#pragma unroll
        for (int o = 16; o; o >>= 1) m = fmaxf(m, __shfl_xor_sync(0xffffffffu, m, o));

        float s = 0.f;
        for (int i = 0; i < 64; i++) s += __expf(row[lane + 32 * i] - m);
#pragma unroll
        for (int o = 16; o; o >>= 1) s += __shfl_xor_sync(0xffffffffu, s, o);
        const float inv = 1.f / s;

        for (int t = 0; t < TOPK_; t++) {
            float lv = cm[0]; int li = ci[0];
#pragma unroll
            for (int c = 1; c < 4; c++)
                if (cm[c] > lv || (cm[c] == lv && ci[c] < li)) { lv = cm[c]; li = ci[c]; }
            float bv = lv; int bi = li;
#pragma unroll
            for (int o = 16; o; o >>= 1) {
                float ov = __shfl_xor_sync(0xffffffffu, bv, o);
                int   oi = __shfl_xor_sync(0xffffffffu, bi, o);
                if (ov > bv || (ov == bv && oi < bi)) { bv = ov; bi = oi; }
            }
            if (lane == 0) {
                swl[wid * TOPK_ + t] = __expf(bv - m) * inv;
                sil[wid * TOPK_ + t] = bi;
            }
            if ((bi & 31) == lane) {
                row[bi] = -INFINITY;
                int cc = (bi - lane) >> 9;   // which chunk
#pragma unroll
                for (int c = 0; c < 4; c++) {
                    if (c == cc) {
                        float nv = -INFINITY; int ni = 0;
                        for (int i = 0; i < 16; i++) {
                            int k = lane + 32 * (c * 16 + i);
                            float v = row[k];
                            if (v > nv) { nv = v; ni = k; }
                        }
                        cm[c] = nv; ci[c] = ni;
                    }
                }
            }
            __syncwarp();
        }
    }
    __syncthreads();

    // ---- Phase 3: sparse AV. 256 threads: (q, 4-dim chunk) each ----
    if (tid < 256) {
        int q = tid >> 4;
        int d = (tid & 15) * 4;
        const float* vb = g_Vh + (size_t)bh * LK_ * 64;
        float4 o = make_float4(0.f, 0.f, 0.f, 0.f);
#pragma unroll
        for (int t = 0; t < TOPK_; t++) {
            float w  = swl[q * TOPK_ + t];
            int  idx = sil[q * TOPK_ + t];
            float4 vv = *(const float4*)(vb + (size_t)idx * 64 + d);
            o.x = fmaf(w, vv.x, o.x);
            o.y = fmaf(w, vv.y, o.y);
            o.z = fmaf(w, vv.z, o.z);
            o.w = fmaf(w, vv.w, o.w);
        }
        *(float4*)&g_AO[((size_t)b * LQ_ + q0 + q) * E_ + h * 64 + d] = o;
    }
}

// ---------------------------------------------------------------------------
extern "C" void kernel_launch(void* const* d_in, const int* in_sizes, int n_in,
                              void* d_out, int out_size)
{
    const float* q  = (const float*)d_in[0];
    const float* k  = (const float*)d_in[1];
    const float* v  = (const float*)d_in[2];
    const float* Wq = (const float*)d_in[3];
    const float* Wk = (const float*)d_in[4];
    const float* Wv = (const float*)d_in[5];
    const float* Wo = (const float*)d_in[6];
    const float* bo = (const float*)d_in[7];
    float* out = (float*)d_out;

    float *pQh, *pKh, *pVh, *pAO;
    cudaGetSymbolAddress((void**)&pQh, g_Qh);
    cudaGetSymbolAddress((void**)&pKh, g_Kh);
    cudaGetSymbolAddress((void**)&pVh, g_Vh);
    cudaGetSymbolAddress((void**)&pAO, g_AO);

    const int smem_attn = (16 * 2048 + 1024 + 320) * 4 + 320 * 4;  // 137728 B
    cudaFuncSetAttribute(attn_topk2, cudaFuncAttributeMaxDynamicSharedMemorySize, smem_attn);

    // projections into head layout
    gemm_nt<0><<<dim3((B_ * LQ_) / 128, E_ / 128), 256>>>(q, Wq, pQh, LQ_, nullptr, nullptr);
    gemm_nt<0><<<dim3((B_ * LK_) / 128, E_ / 128), 256>>>(k, Wk, pKh, LK_, nullptr, nullptr);
    gemm_nt<0><<<dim3((B_ * LK_) / 128, E_ / 128), 256>>>(v, Wv, pVh, LK_, nullptr, nullptr);

    // fused scores + softmax + top-20 + sparse AV
    attn_topk2<<<dim3(LQ_ / 16, H_, B_), 512, smem_attn>>>();

    // output projection + bias + residual(q)
    gemm_nt<1><<<dim3((B_ * LQ_) / 128, E_ / 128), 256>>>(pAO, Wo, out, LQ_, bo, q);
}

// round 10
// speedup vs baseline: 4.3716x; 1.2421x over previous
#include <cuda_runtime.h>
#include <math.h>
#include <stdint.h>

#define B_    8
#define LQ_   512
#define LK_   2048
#define E_    512
#define H_    8
#define HD_   64
#define TOPK_ 20

// ---------------- scratch (static device globals; no allocs) ----------------
__device__ __align__(128) float g_Qh[(size_t)B_ * H_ * LQ_ * HD_];   //  8 MB  [b,h,lq,hd]
__device__ __align__(128) float g_Kt[(size_t)B_ * H_ * HD_ * LK_];   // 32 MB  [b,h,hd,lk]  (TRANSPOSED)
__device__ __align__(128) float g_Vh[(size_t)B_ * H_ * LK_ * HD_];   // 32 MB  [b,h,lk,hd]
__device__ __align__(128) float g_AO[(size_t)B_ * LQ_ * E_];         //  8 MB  [b,lq,e]

// ---------------------------------------------------------------------------
// GEMM  Y = X @ W^T  (X: [M,512], W: [512,512], both row-major K-contiguous)
// BM=128, BN=128, BK=16, 256 threads, 8x8 micro-tile, 2 CTAs/SM.
// MODE 0: scatter into head layout [b,h,l,hd]       (L = rows per batch)
// MODE 1: row-major + bias[n] + resid[m,n]
// MODE 2: transposed head layout [b,h,hd,l]  (coalesced along l=m)
// ---------------------------------------------------------------------------
template <int MODE>
__global__ void __launch_bounds__(256, 2)
gemm_nt(const float* __restrict__ X, const float* __restrict__ W,
        float* __restrict__ Y, int L,
        const float* __restrict__ bias, const float* __restrict__ resid)
{
    __shared__ __align__(16) float As[16][132];  // transposed: As[k][m]
    __shared__ __align__(16) float Bs[16][132];  // transposed: Bs[k][n]

    const int tid = threadIdx.x;
    const int m0  = blockIdx.x * 128;
    const int n0  = blockIdx.y * 128;
    const int ty  = tid >> 4;   // 0..15
    const int tx  = tid & 15;   // 0..15

    float acc[8][8];
#pragma unroll
    for (int i = 0; i < 8; i++)
#pragma unroll
        for (int j = 0; j < 8; j++) acc[i][j] = 0.f;

    for (int kt = 0; kt < E_; kt += 16) {
#pragma unroll
        for (int i = 0; i < 2; i++) {
            int f   = tid + i * 256;
            int row = f >> 2;
            int c4  = (f & 3) * 4;
            float4 v = *(const float4*)(X + (size_t)(m0 + row) * E_ + kt + c4);
            As[c4 + 0][row] = v.x;
            As[c4 + 1][row] = v.y;
            As[c4 + 2][row] = v.z;
            As[c4 + 3][row] = v.w;
        }
#pragma unroll
        for (int i = 0; i < 2; i++) {
            int f   = tid + i * 256;
            int row = f >> 2;
            int c4  = (f & 3) * 4;
            float4 v = *(const float4*)(W + (size_t)(n0 + row) * E_ + kt + c4);
            Bs[c4 + 0][row] = v.x;
            Bs[c4 + 1][row] = v.y;
            Bs[c4 + 2][row] = v.z;
            Bs[c4 + 3][row] = v.w;
        }
        __syncthreads();

#pragma unroll
        for (int kk = 0; kk < 16; kk++) {
            float a[8], b[8];
            *(float4*)(a)     = *(const float4*)&As[kk][ty * 8];
            *(float4*)(a + 4) = *(const float4*)&As[kk][ty * 8 + 4];
            *(float4*)(b)     = *(const float4*)&Bs[kk][tx * 8];
            *(float4*)(b + 4) = *(const float4*)&Bs[kk][tx * 8 + 4];
#pragma unroll
            for (int i = 0; i < 8; i++)
#pragma unroll
                for (int j = 0; j < 8; j++) acc[i][j] = fmaf(a[i], b[j], acc[i][j]);
        }
        __syncthreads();
    }

    if (MODE == 2) {
        // Y[b*512 + n][lk],  lk = m % 2048.  Thread holds 8 consecutive m per n.
        const int bb  = m0 >> 11;                 // LK_=2048, tile never straddles b
        const int lk0 = (m0 & 2047) + ty * 8;
#pragma unroll
        for (int j = 0; j < 8; j++) {
            int n = n0 + tx * 8 + j;
            size_t base = ((size_t)(bb * 512 + n) << 11) + lk0;
            *(float4*)&Y[base]     = make_float4(acc[0][j], acc[1][j], acc[2][j], acc[3][j]);
            *(float4*)&Y[base + 4] = make_float4(acc[4][j], acc[5][j], acc[6][j], acc[7][j]);
        }
        return;
    }

#pragma unroll
    for (int i = 0; i < 8; i++) {
        int m = m0 + ty * 8 + i;
#pragma unroll
        for (int j0 = 0; j0 < 8; j0 += 4) {
            int n = n0 + tx * 8 + j0;
            float4 v = make_float4(acc[i][j0], acc[i][j0 + 1], acc[i][j0 + 2], acc[i][j0 + 3]);
            if (MODE == 0) {
                int bb = m / L, l = m - bb * L;
                int h  = n >> 6, hd = n & 63;
                *(float4*)&Y[(((size_t)(bb * H_ + h) * L + l) << 6) + hd] = v;
            } else {
                float4 bi4 = *(const float4*)&bias[n];
                float4 r4  = *(const float4*)&resid[(size_t)m * E_ + n];
                v.x += bi4.x + r4.x;
                v.y += bi4.y + r4.y;
                v.z += bi4.z + r4.z;
                v.w += bi4.w + r4.w;
                *(float4*)&Y[(size_t)m * E_ + n] = v;
            }
        }
    }
}

// ---------------------------------------------------------------------------
// Attention v3: block = (b, h, 16 queries), 512 threads.
// Phase 1: QK scores from TRANSPOSED K (coalesced; thread owns 4 consecutive
//          keys, covers all 2048 in one pass; 16q x 4k regs) -> smem [16][2048]
// Phase 2: warp-per-query softmax stats + top-20 (chunked lane maxima)
// Phase 3: sparse AV gather (16q x 64d, float4 per thread)
// ---------------------------------------------------------------------------
__global__ void __launch_bounds__(512, 1) attn_topk3()
{
    extern __shared__ float sm[];
    float* scores = sm;                    // 16*2048 floats
    float* Qs     = sm + 16 * 2048;        // 1024 floats [q][d]
    float* swl    = Qs + 1024;             // 16*20 weights
    int*   sil    = (int*)(swl + 320);     // 16*20 indices

    const int tid  = threadIdx.x;
    const int lane = tid & 31;
    const int wid  = tid >> 5;             // 0..15
    const int q0   = blockIdx.x * 16;
    const int h    = blockIdx.y;
    const int b    = blockIdx.z;
    const int bh   = b * H_ + h;

    // ---- load Q tile (scaled) ----
    {
        const float* qsrc = g_Qh + ((size_t)bh * LQ_ + q0) * 64;
        for (int i = tid; i < 1024; i += 512) Qs[i] = qsrc[i] * 0.125f;  // 1/sqrt(64)
    }
    __syncthreads();

    // ---- Phase 1: thread owns keys 4*tid .. 4*tid+3 (coalesced Kt reads) ----
    {
        const float* ktb = g_Kt + ((size_t)bh << 17) + 4 * tid;   // [d][lk], row 2048

        float acc[16][4];
#pragma unroll
        for (int q = 0; q < 16; q++)
#pragma unroll
            for (int j = 0; j < 4; j++) acc[q][j] = 0.f;

#pragma unroll 1
        for (int dc = 0; dc < 16; dc++) {
            // 4 consecutive d-rows, 4 consecutive keys each: fully coalesced
            float4 kv0 = *(const float4*)(ktb + (size_t)(4 * dc + 0) * 2048);
            float4 kv1 = *(const float4*)(ktb + (size_t)(4 * dc + 1) * 2048);
            float4 kv2 = *(const float4*)(ktb + (size_t)(4 * dc + 2) * 2048);
            float4 kv3 = *(const float4*)(ktb + (size_t)(4 * dc + 3) * 2048);
#pragma unroll
            for (int q = 0; q < 16; q++) {
                float4 qv = *(const float4*)&Qs[q * 64 + dc * 4];
                float t0 = acc[q][0], t1 = acc[q][1], t2 = acc[q][2], t3 = acc[q][3];
                t0 = fmaf(qv.x, kv0.x, t0); t1 = fmaf(qv.x, kv0.y, t1);
                t2 = fmaf(qv.x, kv0.z, t2); t3 = fmaf(qv.x, kv0.w, t3);
                t0 = fmaf(qv.y, kv1.x, t0); t1 = fmaf(qv.y, kv1.y, t1);
                t2 = fmaf(qv.y, kv1.z, t2); t3 = fmaf(qv.y, kv1.w, t3);
                t0 = fmaf(qv.z, kv2.x, t0); t1 = fmaf(qv.z, kv2.y, t1);
                t2 = fmaf(qv.z, kv2.z, t2); t3 = fmaf(qv.z, kv2.w, t3);
                t0 = fmaf(qv.w, kv3.x, t0); t1 = fmaf(qv.w, kv3.y, t1);
                t2 = fmaf(qv.w, kv3.z, t2); t3 = fmaf(qv.w, kv3.w, t3);
                acc[q][0] = t0; acc[q][1] = t1; acc[q][2] = t2; acc[q][3] = t3;
            }
        }
#pragma unroll
        for (int q = 0; q < 16; q++)
            *(float4*)&scores[q * 2048 + 4 * tid] =
                make_float4(acc[q][0], acc[q][1], acc[q][2], acc[q][3]);
    }
    __syncthreads();

    // ---- Phase 2: per-warp softmax stats + top-20 for query q = wid ----
    {
        float* row = scores + wid * 2048;   // lane owns k = lane + 32*i, i<64

        float cm[4]; int ci[4];             // chunk maxima (chunks of 16 strided elems)
        float m = -INFINITY;
#pragma unroll
        for (int c = 0; c < 4; c++) {
            float bv = -INFINITY; int bi = 0;
            for (int i = 0; i < 16; i++) {
                int k = lane + 32 * (c * 16 + i);
                float v = row[k];
                if (v > bv) { bv = v; bi = k; }
            }
            cm[c] = bv; ci[c] = bi;
            m = fmaxf(m, bv);
        }
#pragma unroll
        for (int o = 16; o; o >>= 1) m = fmaxf(m, __shfl_xor_sync(0xffffffffu, m, o));

        float s = 0.f;
        for (int i = 0; i < 64; i++) s += __expf(row[lane + 32 * i] - m);
#pragma unroll
        for (int o = 16; o; o >>= 1) s += __shfl_xor_sync(0xffffffffu, s, o);
        const float inv = 1.f / s;

        for (int t = 0; t < TOPK_; t++) {
            float lv = cm[0]; int li = ci[0];
#pragma unroll
            for (int c = 1; c < 4; c++)
                if (cm[c] > lv || (cm[c] == lv && ci[c] < li)) { lv = cm[c]; li = ci[c]; }
            float bv = lv; int bi = li;
#pragma unroll
            for (int o = 16; o; o >>= 1) {
                float ov = __shfl_xor_sync(0xffffffffu, bv, o);
                int   oi = __shfl_xor_sync(0xffffffffu, bi, o);
                if (ov > bv || (ov == bv && oi < bi)) { bv = ov; bi = oi; }
            }
            if (lane == 0) {
                swl[wid * TOPK_ + t] = __expf(bv - m) * inv;
                sil[wid * TOPK_ + t] = bi;
            }
            if ((bi & 31) == lane) {
                row[bi] = -INFINITY;
                int cc = (bi - lane) >> 9;   // which chunk
#pragma unroll
                for (int c = 0; c < 4; c++) {
                    if (c == cc) {
                        float nv = -INFINITY; int ni = 0;
                        for (int i = 0; i < 16; i++) {
                            int k = lane + 32 * (c * 16 + i);
                            float v = row[k];
                            if (v > nv) { nv = v; ni = k; }
                        }
                        cm[c] = nv; ci[c] = ni;
                    }
                }
            }
            __syncwarp();
        }
    }
    __syncthreads();

    // ---- Phase 3: sparse AV. 256 threads: (q, 4-dim chunk) each ----
    if (tid < 256) {
        int q = tid >> 4;
        int d = (tid & 15) * 4;
        const float* vb = g_Vh + (size_t)bh * LK_ * 64;
        float4 o = make_float4(0.f, 0.f, 0.f, 0.f);
#pragma unroll
        for (int t = 0; t < TOPK_; t++) {
            float w  = swl[q * TOPK_ + t];
            int  idx = sil[q * TOPK_ + t];
            float4 vv = *(const float4*)(vb + (size_t)idx * 64 + d);
            o.x = fmaf(w, vv.x, o.x);
            o.y = fmaf(w, vv.y, o.y);
            o.z = fmaf(w, vv.z, o.z);
            o.w = fmaf(w, vv.w, o.w);
        }
        *(float4*)&g_AO[((size_t)b * LQ_ + q0 + q) * E_ + h * 64 + d] = o;
    }
}

// ---------------------------------------------------------------------------
extern "C" void kernel_launch(void* const* d_in, const int* in_sizes, int n_in,
                              void* d_out, int out_size)
{
    const float* q  = (const float*)d_in[0];
    const float* k  = (const float*)d_in[1];
    const float* v  = (const float*)d_in[2];
    const float* Wq = (const float*)d_in[3];
    const float* Wk = (const float*)d_in[4];
    const float* Wv = (const float*)d_in[5];
    const float* Wo = (const float*)d_in[6];
    const float* bo = (const float*)d_in[7];
    float* out = (float*)d_out;

    float *pQh, *pKt, *pVh, *pAO;
    cudaGetSymbolAddress((void**)&pQh, g_Qh);
    cudaGetSymbolAddress((void**)&pKt, g_Kt);
    cudaGetSymbolAddress((void**)&pVh, g_Vh);
    cudaGetSymbolAddress((void**)&pAO, g_AO);

    const int smem_attn = (16 * 2048 + 1024 + 320) * 4 + 320 * 4;  // 137728 B
    cudaFuncSetAttribute(attn_topk3, cudaFuncAttributeMaxDynamicSharedMemorySize, smem_attn);

    // projections
    gemm_nt<0><<<dim3((B_ * LQ_) / 128, E_ / 128), 256>>>(q, Wq, pQh, LQ_, nullptr, nullptr);
    gemm_nt<2><<<dim3((B_ * LK_) / 128, E_ / 128), 256>>>(k, Wk, pKt, LK_, nullptr, nullptr);
    gemm_nt<0><<<dim3((B_ * LK_) / 128, E_ / 128), 256>>>(v, Wv, pVh, LK_, nullptr, nullptr);

    // fused scores + softmax + top-20 + sparse AV
    attn_topk3<<<dim3(LQ_ / 16, H_, B_), 512, smem_attn>>>();

    // output projection + bias + residual(q)
    gemm_nt<1><<<dim3((B_ * LQ_) / 128, E_ / 128), 256>>>(pAO, Wo, out, LQ_, bo, q);
}

// round 12
// speedup vs baseline: 6.4371x; 1.4725x over previous
#include <cuda_runtime.h>
#include <math.h>
#include <stdint.h>

#define B_    8
#define LQ_   512
#define LK_   2048
#define E_    512
#define H_    8
#define HD_   64
#define TOPK_ 20

// ---------------- scratch (static device globals; no allocs) ----------------
__device__ __align__(128) float g_Qh[(size_t)B_ * H_ * LQ_ * HD_];   //  8 MB  [b,h,lq,hd]
__device__ __align__(128) float g_Kt[(size_t)B_ * H_ * HD_ * LK_];   // 32 MB  [b,h,hd,lk]  (TRANSPOSED)
__device__ __align__(128) float g_Vh[(size_t)B_ * H_ * LK_ * HD_];   // 32 MB  [b,h,lk,hd]
__device__ __align__(128) float g_AO[(size_t)B_ * LQ_ * E_];         //  8 MB  [b,lq,e]

// ======================= mma.sync helpers (base ISA) ========================
__device__ __forceinline__ uint32_t smem_u32(const void* p) {
    uint32_t a;
    asm("{ .reg .u64 t; cvta.to.shared.u64 t, %1; cvt.u32.u64 %0, t; }" : "=r"(a) : "l"(p));
    return a;
}
__device__ __forceinline__ uint32_t cvt_tf32(float x) {
    uint32_t r;
    asm("cvt.rna.tf32.f32 %0, %1;" : "=r"(r) : "f"(x));
    return r;
}
__device__ __forceinline__ void ldsm_x4(uint32_t* r, uint32_t addr) {
    asm volatile("ldmatrix.sync.aligned.m8n8.x4.shared.b16 {%0,%1,%2,%3}, [%4];"
                 : "=r"(r[0]), "=r"(r[1]), "=r"(r[2]), "=r"(r[3]) : "r"(addr));
}
__device__ __forceinline__ void ldsm_x2(uint32_t* r, uint32_t addr) {
    asm volatile("ldmatrix.sync.aligned.m8n8.x2.shared.b16 {%0,%1}, [%2];"
                 : "=r"(r[0]), "=r"(r[1]) : "r"(addr));
}
__device__ __forceinline__ void mma_tf32(float* c, const uint32_t* a, const uint32_t* b) {
    asm volatile(
        "mma.sync.aligned.m16n8k8.row.col.f32.tf32.tf32.f32 "
        "{%0,%1,%2,%3}, {%4,%5,%6,%7}, {%8,%9}, {%0,%1,%2,%3};"
        : "+f"(c[0]), "+f"(c[1]), "+f"(c[2]), "+f"(c[3])
        : "r"(a[0]), "r"(a[1]), "r"(a[2]), "r"(a[3]), "r"(b[0]), "r"(b[1]));
}

// ---------------------------------------------------------------------------
// tf32 mma.sync GEMM:  D = A_rows @ B_rows^T  (both [rows][512] K-contiguous)
// CTA tile 128(A-rows) x 128(B-rows), BK=32. 8 warps = 2(m) x 4(n), warp 64x32.
// MODE 0: D[m][n] -> head layout [b,h,l,hd]   (A=X, B=W; L rows per batch)
// MODE 1: D[m][n] -> row-major + bias[n] + resid[m,n]
// MODE 2: A=W, B=X; D[rw][cx] -> Y[(bb*512+rw)*2048 + lk]  (coalesced lk)
// ---------------------------------------------------------------------------
#define PITCH 36

template <int MODE>
__global__ void __launch_bounds__(256, 2)
gemm_mma(const float* __restrict__ A, const float* __restrict__ Bm,
         float* __restrict__ Y, int L,
         const float* __restrict__ bias, const float* __restrict__ resid)
{
    __shared__ __align__(16) float As[128 * PITCH];
    __shared__ __align__(16) float Bs[128 * PITCH];

    const int tid  = threadIdx.x;
    const int lane = tid & 31;
    const int wid  = tid >> 5;
    const int wm   = wid & 1;        // 0..1 : m-offset wm*64
    const int wn   = wid >> 1;       // 0..3 : n-offset wn*32
    const int m0   = blockIdx.x * 128;
    const int n0   = blockIdx.y * 128;

    const uint32_t sA = smem_u32(As);
    const uint32_t sB = smem_u32(Bs);

    // ldmatrix per-lane row/offset patterns
    const int lrA   = (lane & 7) + ((lane >> 3) & 1) * 8;  // row in 16-row frag
    const int koA   = (lane >> 4) * 16;                    // byte offset (k 4..7)
    const int lB    = lane & 15;
    const int lrB   = lB & 7;
    const int koB   = (lB >> 3) * 16;

    // load assignment: 2 threads per row
    const int lrow  = tid >> 1;
    const int lcol  = (tid & 1) * 16;

    float c[4][4][4];
#pragma unroll
    for (int i = 0; i < 4; i++)
#pragma unroll
        for (int j = 0; j < 4; j++)
#pragma unroll
            for (int e = 0; e < 4; e++) c[i][j][e] = 0.f;

    const float* aptr = A  + (size_t)(m0 + lrow) * E_ + lcol;
    const float* bptr = Bm + (size_t)(n0 + lrow) * E_ + lcol;
    float* asw = &As[lrow * PITCH + lcol];
    float* bsw = &Bs[lrow * PITCH + lcol];

    for (int kt = 0; kt < 16; kt++) {
#pragma unroll
        for (int i4 = 0; i4 < 4; i4++) {
            float4 va = *(const float4*)(aptr + kt * 32 + i4 * 4);
            uint4 ta;
            ta.x = cvt_tf32(va.x); ta.y = cvt_tf32(va.y);
            ta.z = cvt_tf32(va.z); ta.w = cvt_tf32(va.w);
            *(uint4*)(asw + i4 * 4) = ta;
            float4 vb = *(const float4*)(bptr + kt * 32 + i4 * 4);
            uint4 tb;
            tb.x = cvt_tf32(vb.x); tb.y = cvt_tf32(vb.y);
            tb.z = cvt_tf32(vb.z); tb.w = cvt_tf32(vb.w);
            *(uint4*)(bsw + i4 * 4) = tb;
        }
        __syncthreads();

#pragma unroll
        for (int ks = 0; ks < 4; ks++) {
            uint32_t a[4][4], b[4][2];
#pragma unroll
            for (int i = 0; i < 4; i++)
                ldsm_x4(a[i], sA + (uint32_t)(((wm * 64 + i * 16 + lrA) * PITCH + ks * 8) * 4 + koA));
#pragma unroll
            for (int j = 0; j < 4; j++)
                ldsm_x2(b[j], sB + (uint32_t)(((wn * 32 + j * 8 + lrB) * PITCH + ks * 8) * 4 + koB));
#pragma unroll
            for (int i = 0; i < 4; i++)
#pragma unroll
                for (int j = 0; j < 4; j++)
                    mma_tf32(c[i][j], a[i], b[j]);
        }
        __syncthreads();
    }

    // ------------------------------ epilogue --------------------------------
    const int rq = lane >> 2;          // 0..7
    const int cq = (lane & 3) * 2;     // 0,2,4,6

#pragma unroll
    for (int i = 0; i < 4; i++) {
#pragma unroll
        for (int j = 0; j < 4; j++) {
#pragma unroll
            for (int half = 0; half < 2; half++) {
                const float v0 = c[i][j][half * 2 + 0];
                const float v1 = c[i][j][half * 2 + 1];
                if (MODE == 2) {
                    int rw = m0 + wm * 64 + i * 16 + rq + half * 8;   // W row (out n)
                    int cx = n0 + wn * 32 + j * 8 + cq;               // X row (b,lk)
                    int bb = cx >> 11, lk = cx & 2047;
                    float2* dst = (float2*)&Y[((size_t)(bb * 512 + rw) << 11) + lk];
                    *dst = make_float2(v0, v1);
                } else {
                    int m = m0 + wm * 64 + i * 16 + rq + half * 8;
                    int n = n0 + wn * 32 + j * 8 + cq;
                    if (MODE == 0) {
                        int bb = m / L, l = m - bb * L;
                        int h = n >> 6, hd = n & 63;
                        *(float2*)&Y[(((size_t)(bb * H_ + h) * L + l) << 6) + hd] =
                            make_float2(v0, v1);
                    } else {
                        float2 bi2 = *(const float2*)&bias[n];
                        float2 r2  = *(const float2*)&resid[(size_t)m * E_ + n];
                        *(float2*)&Y[(size_t)m * E_ + n] =
                            make_float2(v0 + bi2.x + r2.x, v1 + bi2.y + r2.y);
                    }
                }
            }
        }
    }
}

// ---------------------------------------------------------------------------
// Attention v3 (unchanged): block = (b, h, 16 queries), 512 threads.
// ---------------------------------------------------------------------------
__global__ void __launch_bounds__(512, 1) attn_topk3()
{
    extern __shared__ float sm[];
    float* scores = sm;                    // 16*2048 floats
    float* Qs     = sm + 16 * 2048;        // 1024 floats [q][d]
    float* swl    = Qs + 1024;             // 16*20 weights
    int*   sil    = (int*)(swl + 320);     // 16*20 indices

    const int tid  = threadIdx.x;
    const int lane = tid & 31;
    const int wid  = tid >> 5;             // 0..15
    const int q0   = blockIdx.x * 16;
    const int h    = blockIdx.y;
    const int b    = blockIdx.z;
    const int bh   = b * H_ + h;

    {
        const float* qsrc = g_Qh + ((size_t)bh * LQ_ + q0) * 64;
        for (int i = tid; i < 1024; i += 512) Qs[i] = qsrc[i] * 0.125f;  // 1/sqrt(64)
    }
    __syncthreads();

    // ---- Phase 1: thread owns keys 4*tid .. 4*tid+3 (coalesced Kt reads) ----
    {
        const float* ktb = g_Kt + ((size_t)bh << 17) + 4 * tid;   // [d][lk], row 2048

        float acc[16][4];
#pragma unroll
        for (int q = 0; q < 16; q++)
#pragma unroll
            for (int j = 0; j < 4; j++) acc[q][j] = 0.f;

#pragma unroll 1
        for (int dc = 0; dc < 16; dc++) {
            float4 kv0 = *(const float4*)(ktb + (size_t)(4 * dc + 0) * 2048);
            float4 kv1 = *(const float4*)(ktb + (size_t)(4 * dc + 1) * 2048);
            float4 kv2 = *(const float4*)(ktb + (size_t)(4 * dc + 2) * 2048);
            float4 kv3 = *(const float4*)(ktb + (size_t)(4 * dc + 3) * 2048);
#pragma unroll
            for (int q = 0; q < 16; q++) {
                float4 qv = *(const float4*)&Qs[q * 64 + dc * 4];
                float t0 = acc[q][0], t1 = acc[q][1], t2 = acc[q][2], t3 = acc[q][3];
                t0 = fmaf(qv.x, kv0.x, t0); t1 = fmaf(qv.x, kv0.y, t1);
                t2 = fmaf(qv.x, kv0.z, t2); t3 = fmaf(qv.x, kv0.w, t3);
                t0 = fmaf(qv.y, kv1.x, t0); t1 = fmaf(qv.y, kv1.y, t1);
                t2 = fmaf(qv.y, kv1.z, t2); t3 = fmaf(qv.y, kv1.w, t3);
                t0 = fmaf(qv.z, kv2.x, t0); t1 = fmaf(qv.z, kv2.y, t1);
                t2 = fmaf(qv.z, kv2.z, t2); t3 = fmaf(qv.z, kv2.w, t3);
                t0 = fmaf(qv.w, kv3.x, t0); t1 = fmaf(qv.w, kv3.y, t1);
                t2 = fmaf(qv.w, kv3.z, t2); t3 = fmaf(qv.w, kv3.w, t3);
                acc[q][0] = t0; acc[q][1] = t1; acc[q][2] = t2; acc[q][3] = t3;
            }
        }
#pragma unroll
        for (int q = 0; q < 16; q++)
            *(float4*)&scores[q * 2048 + 4 * tid] =
                make_float4(acc[q][0], acc[q][1], acc[q][2], acc[q][3]);
    }
    __syncthreads();

    // ---- Phase 2: per-warp softmax stats + top-20 for query q = wid ----
    {
        float* row = scores + wid * 2048;

        float cm[4]; int ci[4];
        float m = -INFINITY;
#pragma unroll
        for (int c = 0; c < 4; c++) {
            float bv = -INFINITY; int bi = 0;
            for (int i = 0; i < 16; i++) {
                int k = lane + 32 * (c * 16 + i);
                float v = row[k];
                if (v > bv) { bv = v; bi = k; }
            }
            cm[c] = bv; ci[c] = bi;
            m = fmaxf(m, bv);
        }
#pragma unroll
        for (int o = 16; o; o >>= 1) m = fmaxf(m, __shfl_xor_sync(0xffffffffu, m, o));

        float s = 0.f;
        for (int i = 0; i < 64; i++) s += __expf(row[lane + 32 * i] - m);
#pragma unroll
        for (int o = 16; o; o >>= 1) s += __shfl_xor_sync(0xffffffffu, s, o);
        const float inv = 1.f / s;

        for (int t = 0; t < TOPK_; t++) {
            float lv = cm[0]; int li = ci[0];
#pragma unroll
            for (int c = 1; c < 4; c++)
                if (cm[c] > lv || (cm[c] == lv && ci[c] < li)) { lv = cm[c]; li = ci[c]; }
            float bv = lv; int bi = li;
#pragma unroll
            for (int o = 16; o; o >>= 1) {
                float ov = __shfl_xor_sync(0xffffffffu, bv, o);
                int   oi = __shfl_xor_sync(0xffffffffu, bi, o);
                if (ov > bv || (ov == bv && oi < bi)) { bv = ov; bi = oi; }
            }
            if (lane == 0) {
                swl[wid * TOPK_ + t] = __expf(bv - m) * inv;
                sil[wid * TOPK_ + t] = bi;
            }
            if ((bi & 31) == lane) {
                row[bi] = -INFINITY;
                int cc = (bi - lane) >> 9;
#pragma unroll
                for (int c = 0; c < 4; c++) {
                    if (c == cc) {
                        float nv = -INFINITY; int ni = 0;
                        for (int i = 0; i < 16; i++) {
                            int k = lane + 32 * (c * 16 + i);
                            float v = row[k];
                            if (v > nv) { nv = v; ni = k; }
                        }
                        cm[c] = nv; ci[c] = ni;
                    }
                }
            }
            __syncwarp();
        }
    }
    __syncthreads();

    // ---- Phase 3: sparse AV. 256 threads: (q, 4-dim chunk) each ----
    if (tid < 256) {
        int q = tid >> 4;
        int d = (tid & 15) * 4;
        const float* vb = g_Vh + (size_t)bh * LK_ * 64;
        float4 o = make_float4(0.f, 0.f, 0.f, 0.f);
#pragma unroll
        for (int t = 0; t < TOPK_; t++) {
            float w  = swl[q * TOPK_ + t];
            int  idx = sil[q * TOPK_ + t];
            float4 vv = *(const float4*)(vb + (size_t)idx * 64 + d);
            o.x = fmaf(w, vv.x, o.x);
            o.y = fmaf(w, vv.y, o.y);
            o.z = fmaf(w, vv.z, o.z);
            o.w = fmaf(w, vv.w, o.w);
        }
        *(float4*)&g_AO[((size_t)b * LQ_ + q0 + q) * E_ + h * 64 + d] = o;
    }
}

// ---------------------------------------------------------------------------
extern "C" void kernel_launch(void* const* d_in, const int* in_sizes, int n_in,
                              void* d_out, int out_size)
{
    const float* q  = (const float*)d_in[0];
    const float* k  = (const float*)d_in[1];
    const float* v  = (const float*)d_in[2];
    const float* Wq = (const float*)d_in[3];
    const float* Wk = (const float*)d_in[4];
    const float* Wv = (const float*)d_in[5];
    const float* Wo = (const float*)d_in[6];
    const float* bo = (const float*)d_in[7];
    float* out = (float*)d_out;

    float *pQh, *pKt, *pVh, *pAO;
    cudaGetSymbolAddress((void**)&pQh, g_Qh);
    cudaGetSymbolAddress((void**)&pKt, g_Kt);
    cudaGetSymbolAddress((void**)&pVh, g_Vh);
    cudaGetSymbolAddress((void**)&pAO, g_AO);

    const int smem_attn = (16 * 2048 + 1024 + 320) * 4 + 320 * 4;  // 137728 B
    cudaFuncSetAttribute(attn_topk3, cudaFuncAttributeMaxDynamicSharedMemorySize, smem_attn);

    // projections (tf32 mma.sync)
    gemm_mma<0><<<dim3((B_ * LQ_) / 128, 4), 256>>>(q, Wq, pQh, LQ_, nullptr, nullptr);
    gemm_mma<2><<<dim3(4, (B_ * LK_) / 128), 256>>>(Wk, k, pKt, LK_, nullptr, nullptr);
    gemm_mma<0><<<dim3((B_ * LK_) / 128, 4), 256>>>(v, Wv, pVh, LK_, nullptr, nullptr);

    // fused scores + softmax + top-20 + sparse AV
    attn_topk3<<<dim3(LQ_ / 16, H_, B_), 512, smem_attn>>>();

    // output projection + bias + residual(q)
    gemm_mma<1><<<dim3((B_ * LQ_) / 128, 4), 256>>>(pAO, Wo, out, LQ_, bo, q);
}